// round 5
// baseline (speedup 1.0000x reference)
#include <cuda_runtime.h>
#include <float.h>
#include <limits.h>

#define B_       16
#define C_       80
#define N_       25200
#define N0_      19200
#define N1_      4800
#define N2_      1200
#define K_       25
#define NEG      (-1e30f)
#define SCORE_T  0.55f
#define NBUCK    1024
#define CAP      256
#define BSCALE   (NBUCK / (1.0f - SCORE_T))
#define TILE_A   64
#define MAXC     3584
#define NCELL    (B_ * C_)

// rn32(inter/un) > 0.5  <=>  inter > (0.5 + 2^-25) * un   (exact in double)
#define IOU_EDGE 0.500000029802322387695312500

// candidate key: fbits(score)<<32 | (0x7FFF - n)   (desc sort => score desc, n asc)
__device__ unsigned long long g_cand[NCELL * MAXC];   // ~36.7 MB
__device__ int   g_cnt[NCELL];
__device__ float g_kb[NCELL * K_ * 4];
__device__ float g_ks[NCELL * K_];

// ---------------------------------------------------------------------------
__global__ void zero_kernel()
{
    int i = blockIdx.x * blockDim.x + threadIdx.x;
    if (i < NCELL) g_cnt[i] = 0;
}

// ---------------------------------------------------------------------------
// Kernel 1: fused score + threshold + scatter to per-(b,c) candidate lists.
// grid = B_ * 394, block = 256. Coalesced reads; warp-aggregated appends.
// ---------------------------------------------------------------------------
__global__ __launch_bounds__(256) void scatter_kernel(
    const float* __restrict__ conf0, const float* __restrict__ cls0,
    const float* __restrict__ conf1, const float* __restrict__ cls1,
    const float* __restrict__ conf2, const float* __restrict__ cls2)
{
    __shared__ float s_tile[TILE_A][81];
    __shared__ float s_conf[TILE_A];

    const int NT   = (N_ + TILE_A - 1) / TILE_A;     // 394
    const int b    = blockIdx.x / NT;
    const int t    = blockIdx.x - b * NT;
    const int n0   = t * TILE_A;
    const int tid  = threadIdx.x;
    const int lane = tid & 31;
    const int w    = tid >> 5;
    const int va   = min(TILE_A, N_ - n0);
    const unsigned lmask = (1u << lane) - 1u;

    const float *cf, *cl;
    int loc_base;
    if (n0 < N0_)             { cf = conf0; cl = cls0; loc_base = b * N0_ + n0; }
    else if (n0 < N0_ + N1_)  { cf = conf1; cl = cls1; loc_base = b * N1_ + (n0 - N0_); }
    else                      { cf = conf2; cl = cls2; loc_base = b * N2_ + (n0 - N0_ - N1_); }

    for (int v = tid; v < TILE_A * (C_ / 4); v += 256) {   // 64 * 20
        int a = v / 20, q = v - a * 20;
        if (a < va) {
            float4 t4 = ((const float4*)(cl + (size_t)(loc_base + a) * C_))[q];
            s_tile[a][q * 4 + 0] = t4.x;
            s_tile[a][q * 4 + 1] = t4.y;
            s_tile[a][q * 4 + 2] = t4.z;
            s_tile[a][q * 4 + 3] = t4.w;
        }
    }
    if (tid < va) s_conf[tid] = cf[loc_base + tid];
    __syncthreads();

    // warp w handles classes [w*10, w*10+10); lane = anchor within half-tile
    #pragma unroll
    for (int cc = 0; cc < 10; cc++) {
        int c = w * 10 + cc;
        int cell = b * C_ + c;
        #pragma unroll
        for (int h = 0; h < 2; h++) {
            int a = h * 32 + lane;
            bool pred = false;
            float sc = 0.f;
            if (a < va) {
                sc = s_conf[a] * s_tile[a][c];       // same single f32 mul as reference
                pred = sc > SCORE_T;
            }
            unsigned m = __ballot_sync(0xffffffffu, pred);
            if (m) {
                int base;
                if (lane == 0) base = atomicAdd(&g_cnt[cell], __popc(m));
                base = __shfl_sync(0xffffffffu, base, 0);
                if (pred) {
                    int pos = base + __popc(m & lmask);
                    if (pos < MAXC) {
                        int n = n0 + a;
                        g_cand[(size_t)cell * MAXC + pos] =
                            ((unsigned long long)__float_as_uint(sc) << 32)
                          | (unsigned long long)(0x7FFF - n);
                    }
                }
            }
        }
    }
}

// ---------------------------------------------------------------------------
// Kernel 2: per-(b,c) NMS. Candidate list lives in smem; histogram banding +
// bitonic sort + single-warp greedy walk. grid = NCELL, block = 256.
// ---------------------------------------------------------------------------
__global__ __launch_bounds__(256) void nms_kernel(
    const float* __restrict__ bbox0,
    const float* __restrict__ bbox1,
    const float* __restrict__ bbox2)
{
    __shared__ unsigned long long s_cand[MAXC];   // 28672 B
    __shared__ int    hist[NBUCK];                // 4096 B (becomes suffix-sum S)
    __shared__ int    ct[256];
    __shared__ int    wt[8];
    __shared__ unsigned long long keys[CAP];      // 2048 B
    __shared__ float4 c_box[CAP];                 // 4096 B
    __shared__ int    sh_cnt, sh_lo, sh_nk, sh_Shi;
    __shared__ int    red[8];

    const int tid  = threadIdx.x;
    const int lane = tid & 31;
    const int wrp  = tid >> 5;
    const int cell = blockIdx.x;
    const int b    = cell / C_;
    const int out_base = cell * K_;

    const int cnt = min(g_cnt[cell], MAXC);

    for (int i = tid; i < NBUCK; i += 256) hist[i] = 0;
    if (tid == 0) { sh_nk = 0; sh_Shi = 0; }
    __syncthreads();

    // load candidates + build histogram
    for (int i = tid; i < cnt; i += 256) {
        unsigned long long k = g_cand[(size_t)cell * MAXC + i];
        s_cand[i] = k;
        float sc = __uint_as_float((unsigned)(k >> 32));
        int bkt = min((int)((sc - SCORE_T) * BSCALE), NBUCK - 1);
        atomicAdd(&hist[bkt], 1);
    }
    __syncthreads();

    // parallel suffix sum: hist[i] := S[i] = sum_{j>=i} hist[j]
    {
        int h0 = hist[4 * tid], h1 = hist[4 * tid + 1],
            h2 = hist[4 * tid + 2], h3 = hist[4 * tid + 3];
        int s3 = h3, s2 = h2 + s3, s1 = h1 + s2, s0 = h0 + s1;
        ct[tid] = s0;
        __syncthreads();
        int v = ct[tid];
        #pragma unroll
        for (int off = 1; off < 32; off <<= 1) {
            int u = __shfl_down_sync(0xffffffffu, v, off);
            if (lane + off < 32) v += u;
        }
        if (lane == 0) wt[wrp] = v;
        __syncthreads();
        int addw = 0;
        #pragma unroll
        for (int w2 = 0; w2 < 8; w2++) if (w2 > wrp) addw += wt[w2];
        int T = v + addw - ct[tid];     // sum over chunks > tid
        hist[4 * tid]     = T + s0;
        hist[4 * tid + 1] = T + s1;
        hist[4 * tid + 2] = T + s2;
        hist[4 * tid + 3] = T + s3;
    }
    __syncthreads();

    // kept boxes live in warp-0 registers (lane l = kept[l])
    float ky1 = 0.f, kx1 = 0.f, ky2 = 0.f, kx2 = 0.f, karea = 0.f;

    int hi = NBUCK;
    while (sh_nk < K_ && sh_Shi < cnt && hi > 0) {
        const int S_hi = sh_Shi;

        // find lo = min i < hi with S[i] - S_hi <= CAP (S monotone non-increasing)
        int best = INT_MAX;
        #pragma unroll
        for (int j = 0; j < 4; j++) {
            int i = 4 * tid + j;
            if (i < hi && hist[i] - S_hi <= CAP) { best = min(best, i); }
        }
        #pragma unroll
        for (int off = 16; off; off >>= 1)
            best = min(best, __shfl_down_sync(0xffffffffu, best, off));
        if (lane == 0) red[wrp] = best;
        __syncthreads();
        if (tid == 0) {
            int m = INT_MAX;
            #pragma unroll
            for (int w2 = 0; w2 < 8; w2++) m = min(m, red[w2]);
            sh_lo = (m >= hi) ? hi - 1 : m;
            sh_cnt = 0;
        }
        __syncthreads();
        const int lo = sh_lo;

        // extract band [lo, hi) from the smem candidate list
        for (int i = tid; i < cnt; i += 256) {
            unsigned long long k = s_cand[i];
            float sc = __uint_as_float((unsigned)(k >> 32));
            int bkt = min((int)((sc - SCORE_T) * BSCALE), NBUCK - 1);
            if (bkt >= lo && bkt < hi) {
                int pos = atomicAdd(&sh_cnt, 1);
                if (pos < CAP) keys[pos] = k;
            }
        }
        __syncthreads();
        int bandc = min(sh_cnt, CAP);

        if (bandc > 0) {
            // bitonic sort descending
            int nsort = 32;
            while (nsort < bandc) nsort <<= 1;
            for (int j = bandc + tid; j < nsort; j += 256) keys[j] = 0ull;
            __syncthreads();
            for (int k2 = 2; k2 <= nsort; k2 <<= 1) {
                for (int j = k2 >> 1; j > 0; j >>= 1) {
                    if (tid < nsort) {
                        int p = tid ^ j;
                        if (p > tid) {
                            unsigned long long a = keys[tid], q = keys[p];
                            bool dir = ((tid & k2) == 0);
                            if ((q > a) == dir) { keys[tid] = q; keys[p] = a; }
                        }
                    }
                    __syncthreads();
                }
            }

            // gather boxes for the sorted band
            for (int j = tid; j < bandc; j += 256) {
                int n = 0x7FFF - (int)(keys[j] & 0x7FFFull);
                const float* bb; int loc;
                if (n < N0_)            { bb = bbox0; loc = b * N0_ + n; }
                else if (n < N0_ + N1_) { bb = bbox1; loc = b * N1_ + (n - N0_); }
                else                    { bb = bbox2; loc = b * N2_ + (n - N0_ - N1_); }
                float4 t = ((const float4*)bb)[loc];
                t.x = fmaxf(t.x, 0.f); t.y = fmaxf(t.y, 0.f);
                t.z = fmaxf(t.z, 0.f); t.w = fmaxf(t.w, 0.f);
                c_box[j] = t;
            }
            __syncthreads();

            // greedy walk (warp 0)
            if (tid < 32) {
                int nk = sh_nk;
                for (int j = 0; j < bandc && nk < K_; j++) {
                    float sc = __uint_as_float((unsigned)(keys[j] >> 32));
                    float4 bx = c_box[j];
                    float y1 = fminf(bx.x, bx.z), y2 = fmaxf(bx.x, bx.z);
                    float x1 = fminf(bx.y, bx.w), x2 = fmaxf(bx.y, bx.w);
                    float ar = (y2 - y1) * (x2 - x1);
                    bool sup = false;
                    if (lane < nk) {
                        float ih = fmaxf(fminf(y2, ky2) - fmaxf(y1, ky1), 0.f);
                        float iw = fmaxf(fminf(x2, kx2) - fmaxf(x1, kx1), 0.f);
                        float inter = ih * iw;
                        float un = ar + karea - inter;
                        sup = (un > 0.f) && ((double)inter > IOU_EDGE * (double)un);
                    }
                    if (!__any_sync(0xffffffffu, sup)) {
                        if (lane == nk) { ky1 = y1; kx1 = x1; ky2 = y2; kx2 = x2; karea = ar; }
                        if (lane == 0) {
                            g_ks[out_base + nk] = sc;
                            ((float4*)g_kb)[out_base + nk] = bx;
                        }
                        nk++;
                    }
                }
                if (lane == 0) sh_nk = nk;
            }
        }
        if (tid == 0) sh_Shi = hist[lo];    // processed = S[lo]
        hi = lo;
        __syncthreads();
    }

    const int nkf = sh_nk;
    for (int kk = nkf + tid; kk < K_; kk += 256) {
        g_ks[out_base + kk] = NEG;
        ((float4*)g_kb)[out_base + kk] = make_float4(0.f, 0.f, 0.f, 0.f);
    }
}

// ---------------------------------------------------------------------------
// Kernel 3: per-batch cross-class top-K_. grid = B_, block = 256.
// Output (f32): boxes [B,K,4] | scores [B,K] | cls [B,K] | valid [B]
// ---------------------------------------------------------------------------
__global__ __launch_bounds__(256) void topk_kernel(float* __restrict__ out)
{
    __shared__ float s_s[C_ * K_];
    __shared__ float s_rs[8];
    __shared__ int   s_ri[8];
    __shared__ float sh_s[K_];
    __shared__ int   sh_i[K_];

    const int b    = blockIdx.x;
    const int tid  = threadIdx.x;
    const int lane = tid & 31;

    for (int j = tid; j < C_ * K_; j += 256) s_s[j] = g_ks[b * C_ * K_ + j];
    __syncthreads();

    for (int k = 0; k < K_; k++) {
        float best = -FLT_MAX; int bi = -1;
        for (int i = tid; i < C_ * K_; i += 256) {
            float s = s_s[i];
            if (s > best) { best = s; bi = i; }
        }
        #pragma unroll
        for (int off = 16; off; off >>= 1) {
            float s2 = __shfl_down_sync(0xffffffffu, best, off);
            int   i2 = __shfl_down_sync(0xffffffffu, bi, off);
            if (s2 > best || (s2 == best && (unsigned)i2 < (unsigned)bi)) { best = s2; bi = i2; }
        }
        if (lane == 0) { s_rs[tid >> 5] = best; s_ri[tid >> 5] = bi; }
        __syncthreads();
        if (tid < 32) {
            best = (tid < 8) ? s_rs[tid] : -FLT_MAX;
            bi   = (tid < 8) ? s_ri[tid] : -1;
            #pragma unroll
            for (int off = 4; off; off >>= 1) {
                float s2 = __shfl_down_sync(0xffffffffu, best, off);
                int   i2 = __shfl_down_sync(0xffffffffu, bi, off);
                if (s2 > best || (s2 == best && (unsigned)i2 < (unsigned)bi)) { best = s2; bi = i2; }
            }
            if (tid == 0) {
                sh_s[k] = best; sh_i[k] = bi;
                s_s[bi] = -FLT_MAX;
            }
        }
        __syncthreads();
    }

    const int OB_scores = B_ * K_ * 4;
    const int OB_cls    = OB_scores + B_ * K_;
    const int OB_valid  = OB_cls + B_ * K_;

    if (tid < K_) {
        float s   = sh_s[tid];
        int   idx = sh_i[tid];
        bool  valid = s > SCORE_T;
        float4 bx = make_float4(0.f, 0.f, 0.f, 0.f);
        if (valid) {
            bx = ((float4*)g_kb)[b * C_ * K_ + idx];
            bx.x = fminf(fmaxf(bx.x, 0.f), 1.f);
            bx.y = fminf(fmaxf(bx.y, 0.f), 1.f);
            bx.z = fminf(fmaxf(bx.z, 0.f), 1.f);
            bx.w = fminf(fmaxf(bx.w, 0.f), 1.f);
        }
        int o = b * K_ + tid;
        ((float4*)out)[o]  = bx;
        out[OB_scores + o] = valid ? s : 0.f;
        out[OB_cls + o]    = valid ? (float)(idx / K_) : 0.f;
    }
    if (tid < 32) {
        bool v = (tid < K_) && (sh_s[tid] > SCORE_T);
        unsigned m = __ballot_sync(0xffffffffu, v);
        if (tid == 0) out[OB_valid + b] = (float)__popc(m);
    }
}

// ---------------------------------------------------------------------------
extern "C" void kernel_launch(void* const* d_in, const int* in_sizes, int n_in,
                              void* d_out, int out_size)
{
    const float* bbox0 = (const float*)d_in[0];
    const float* conf0 = (const float*)d_in[1];
    const float* cls0  = (const float*)d_in[2];
    const float* bbox1 = (const float*)d_in[3];
    const float* conf1 = (const float*)d_in[4];
    const float* cls1  = (const float*)d_in[5];
    const float* bbox2 = (const float*)d_in[6];
    const float* conf2 = (const float*)d_in[7];
    const float* cls2  = (const float*)d_in[8];

    const int NT = (N_ + TILE_A - 1) / TILE_A;
    zero_kernel<<<(NCELL + 255) / 256, 256>>>();
    scatter_kernel<<<B_ * NT, 256>>>(conf0, cls0, conf1, cls1, conf2, cls2);
    nms_kernel<<<NCELL, 256>>>(bbox0, bbox1, bbox2);
    topk_kernel<<<B_, 256>>>((float*)d_out);
}

// round 8
// speedup vs baseline: 3.4007x; 3.4007x over previous
#include <cuda_runtime.h>
#include <float.h>
#include <limits.h>

#define B_       16
#define C_       80
#define N_       25200
#define N0_      19200
#define N1_      4800
#define N2_      1200
#define K_       25
#define NEG      (-1e30f)
#define SCORE_T  0.55f
#define NBUCK    1024
#define HB       768          // top band: bucket >= HB  <=> score >~ 0.8875
#define BCAP     512
#define BSCALE   (NBUCK / (1.0f - SCORE_T))
#define NCELL    (B_ * C_)
#define TK_BK0   0x7E199      // fbits(0.55f) >> 11

// rn32(inter/un) > 0.5  <=>  inter > (0.5 + 2^-25) * un   (exact in double)
#define IOU_EDGE 0.500000029802322387695312500

// key: fbits(score)<<32 | (0x7FFF - n)  (u64 desc sort => score desc, n asc)
__device__ unsigned long long g_band[NCELL * BCAP];   // 5.2 MB
__device__ int   g_bandcnt[NCELL];
__device__ float g_kb[NCELL * K_ * 4];
__device__ float g_ks[NCELL * K_];

// ---------------------------------------------------------------------------
__global__ void zero_kernel()
{
    int i = blockIdx.x * blockDim.x + threadIdx.x;
    if (i < NCELL) g_bandcnt[i] = 0;
}

// ---------------------------------------------------------------------------
// Kernel A: stream all cls/conf once; append only top-band candidates.
// Warp chunk = 160 consecutive float4 (8 anchors x 80 classes). No smem.
// ---------------------------------------------------------------------------
__global__ __launch_bounds__(256) void band_scatter(
    const float* __restrict__ conf0, const float* __restrict__ cls0,
    const float* __restrict__ conf1, const float* __restrict__ cls1,
    const float* __restrict__ conf2, const float* __restrict__ cls2)
{
    const int F    = B_ * N_ * 20;                    // 8,064,000 float4 (mult of 160)
    const int gw   = (blockIdx.x * 256 + threadIdx.x) >> 5;
    const int lane = threadIdx.x & 31;
    const int nw   = (gridDim.x * 256) >> 5;

    for (int base = gw * 160; base < F; base += nw * 160) {
        float4 p[5]; float cv[5]; int nn[5], qq[5], bb[5];
        // address generation first, then all 10 loads back-to-back (MLP)
        const float4* cl4a[5]; const float* cfa[5]; int loca[5];
        #pragma unroll
        for (int j = 0; j < 5; j++) {
            int f = base + j * 32 + lane;
            int a = f / 20, q = f - a * 20;
            int b = a / N_, n = a - b * N_;
            const float* cf; const float4* cl4; int loc;
            if (n < N0_)             { cf = conf0; cl4 = (const float4*)cls0; loc = b * N0_ + n; }
            else if (n < N0_ + N1_)  { cf = conf1; cl4 = (const float4*)cls1; loc = b * N1_ + (n - N0_); }
            else                     { cf = conf2; cl4 = (const float4*)cls2; loc = b * N2_ + (n - N0_ - N1_); }
            cl4a[j] = cl4 + (size_t)loc * 20 + q;
            cfa[j]  = cf + loc;
            nn[j] = n; qq[j] = q; bb[j] = b;
        }
        #pragma unroll
        for (int j = 0; j < 5; j++) p[j] = *cl4a[j];
        #pragma unroll
        for (int j = 0; j < 5; j++) cv[j] = *cfa[j];

        #pragma unroll
        for (int j = 0; j < 5; j++) {
            #pragma unroll
            for (int e = 0; e < 4; e++) {
                float pv = (e == 0) ? p[j].x : (e == 1) ? p[j].y : (e == 2) ? p[j].z : p[j].w;
                float sc = cv[j] * pv;                 // same single f32 mul as reference
                if (sc > SCORE_T) {
                    int bkt = min((int)((sc - SCORE_T) * BSCALE), NBUCK - 1);
                    if (bkt >= HB) {
                        int cell = bb[j] * C_ + qq[j] * 4 + e;
                        int pos = atomicAdd(&g_bandcnt[cell], 1);
                        if (pos < BCAP)
                            g_band[(size_t)cell * BCAP + pos] =
                                ((unsigned long long)__float_as_uint(sc) << 32)
                              | (unsigned long long)(0x7FFF - nn[j]);
                    }
                }
            }
        }
    }
}

// ---------------------------------------------------------------------------
// shared helpers
// ---------------------------------------------------------------------------
__device__ __forceinline__ void bitonic_desc(unsigned long long* keys, int cnt, int tid)
{
    int nsort = 32;
    while (nsort < cnt) nsort <<= 1;
    for (int j = cnt + tid; j < nsort; j += 256) keys[j] = 0ull;
    __syncthreads();
    for (int k2 = 2; k2 <= nsort; k2 <<= 1) {
        for (int j = k2 >> 1; j > 0; j >>= 1) {
            for (int i = tid; i < nsort; i += 256) {
                int pp = i ^ j;
                if (pp > i) {
                    unsigned long long a = keys[i], q = keys[pp];
                    bool dir = ((i & k2) == 0);
                    if ((q > a) == dir) { keys[i] = q; keys[pp] = a; }
                }
            }
            __syncthreads();
        }
    }
}

// greedy walk over sorted band; called by warp 0 (tid<32) only.
__device__ __forceinline__ void greedy_walk(
    const unsigned long long* keys, const float4* c_box, int bandc,
    int lane, int out_base,
    float& ky1, float& kx1, float& ky2, float& kx2, float& karea, int* sh_nk)
{
    int nk = *sh_nk;
    for (int j = 0; j < bandc && nk < K_; j++) {
        unsigned long long kk = keys[j];
        if (kk == 0ull) break;
        float  sc = __uint_as_float((unsigned)(kk >> 32));
        float4 bx = c_box[j];
        float y1 = fminf(bx.x, bx.z), y2 = fmaxf(bx.x, bx.z);
        float x1 = fminf(bx.y, bx.w), x2 = fmaxf(bx.y, bx.w);
        float ar = (y2 - y1) * (x2 - x1);
        bool sup = false;
        if (lane < nk) {
            float ih = fmaxf(fminf(y2, ky2) - fmaxf(y1, ky1), 0.f);
            float iw = fmaxf(fminf(x2, kx2) - fmaxf(x1, kx1), 0.f);
            float inter = ih * iw;
            float un = ar + karea - inter;
            sup = (un > 0.f) && ((double)inter > IOU_EDGE * (double)un);
        }
        if (!__any_sync(0xffffffffu, sup)) {
            if (lane == nk) { ky1 = y1; kx1 = x1; ky2 = y2; kx2 = x2; karea = ar; }
            if (lane == 0) {
                g_ks[out_base + nk] = sc;
                ((float4*)g_kb)[out_base + nk] = bx;
            }
            nk++;
        }
    }
    if (lane == 0) *sh_nk = nk;
}

__device__ __forceinline__ float score_at(
    int b, int c, int n,
    const float* conf0, const float* cls0,
    const float* conf1, const float* cls1,
    const float* conf2, const float* cls2)
{
    const float *cf, *cl; int loc;
    if (n < N0_)             { cf = conf0; cl = cls0; loc = b * N0_ + n; }
    else if (n < N0_ + N1_)  { cf = conf1; cl = cls1; loc = b * N1_ + (n - N0_); }
    else                     { cf = conf2; cl = cls2; loc = b * N2_ + (n - N0_ - N1_); }
    return cf[loc] * cl[(size_t)loc * C_ + c];
}

// ---------------------------------------------------------------------------
// Kernel B: per-(b,c) NMS. Common path: sorted top-band walk (no dense read).
// Exact fallback: recompute-from-inputs histogram banding (rare).
// ---------------------------------------------------------------------------
__global__ __launch_bounds__(256) void nms_kernel(
    const float* __restrict__ bbox0, const float* __restrict__ bbox1,
    const float* __restrict__ bbox2,
    const float* __restrict__ conf0, const float* __restrict__ cls0,
    const float* __restrict__ conf1, const float* __restrict__ cls1,
    const float* __restrict__ conf2, const float* __restrict__ cls2)
{
    __shared__ unsigned long long keys[BCAP];     // 4 KB
    __shared__ float4 c_box[BCAP];                // 8 KB
    __shared__ int    hist[NBUCK];                // 4 KB (fallback)
    __shared__ int    ct[256];
    __shared__ int    wt[8];
    __shared__ int    red[8];
    __shared__ int    sh_cnt, sh_nk, sh_lo, sh_Shi;

    const int tid  = threadIdx.x;
    const int lane = tid & 31;
    const int wrp  = tid >> 5;
    const int cell = blockIdx.x;
    const int b    = cell / C_;
    const int c    = cell - b * C_;
    const int out_base = cell * K_;

    const int  cnt_raw  = g_bandcnt[cell];
    const bool overflow = cnt_raw > BCAP;

    if (tid == 0) sh_nk = 0;
    __syncthreads();

    // kept boxes live in warp-0 registers (lane l = kept[l])
    float ky1 = 0.f, kx1 = 0.f, ky2 = 0.f, kx2 = 0.f, karea = 0.f;

    // ---- common path: sorted top-band walk
    if (!overflow && cnt_raw > 0) {
        const int bandc = cnt_raw;
        for (int i = tid; i < bandc; i += 256)
            keys[i] = g_band[(size_t)cell * BCAP + i];
        __syncthreads();
        bitonic_desc(keys, bandc, tid);
        for (int j = tid; j < bandc; j += 256) {
            int n = 0x7FFF - (int)(keys[j] & 0x7FFFull);
            const float* bb; int loc;
            if (n < N0_)             { bb = bbox0; loc = b * N0_ + n; }
            else if (n < N0_ + N1_)  { bb = bbox1; loc = b * N1_ + (n - N0_); }
            else                     { bb = bbox2; loc = b * N2_ + (n - N0_ - N1_); }
            float4 t = ((const float4*)bb)[loc];
            t.x = fmaxf(t.x, 0.f); t.y = fmaxf(t.y, 0.f);
            t.z = fmaxf(t.z, 0.f); t.w = fmaxf(t.w, 0.f);
            c_box[j] = t;
        }
        __syncthreads();
        if (tid < 32)
            greedy_walk(keys, c_box, bandc, lane, out_base, ky1, kx1, ky2, kx2, karea, &sh_nk);
        __syncthreads();
    }

    // ---- fallback: walk buckets below the band (or full restart on overflow)
    if (sh_nk < K_) {
        const int hi_start = overflow ? NBUCK : HB;
        if (overflow && tid == 0) sh_nk = 0;      // restart from scratch
        for (int i = tid; i < NBUCK; i += 256) hist[i] = 0;
        if (tid == 0) sh_Shi = 0;
        __syncthreads();

        for (int n = tid; n < N_; n += 256) {
            float sc = score_at(b, c, n, conf0, cls0, conf1, cls1, conf2, cls2);
            if (sc > SCORE_T) {
                int bkt = min((int)((sc - SCORE_T) * BSCALE), NBUCK - 1);
                if (bkt < hi_start) atomicAdd(&hist[bkt], 1);
            }
        }
        __syncthreads();

        // suffix sum: hist[i] := S[i] = sum_{j>=i} hist[j]
        {
            int h0 = hist[4 * tid], h1 = hist[4 * tid + 1],
                h2 = hist[4 * tid + 2], h3 = hist[4 * tid + 3];
            int s3 = h3, s2 = h2 + s3, s1 = h1 + s2, s0 = h0 + s1;
            ct[tid] = s0;
            __syncthreads();
            int v = ct[tid];
            #pragma unroll
            for (int off = 1; off < 32; off <<= 1) {
                int u = __shfl_down_sync(0xffffffffu, v, off);
                if (lane + off < 32) v += u;
            }
            if (lane == 0) wt[wrp] = v;
            __syncthreads();
            int addw = 0;
            #pragma unroll
            for (int w2 = 0; w2 < 8; w2++) if (w2 > wrp) addw += wt[w2];
            int T = v + addw - ct[tid];
            hist[4 * tid]     = T + s0;
            hist[4 * tid + 1] = T + s1;
            hist[4 * tid + 2] = T + s2;
            hist[4 * tid + 3] = T + s3;
        }
        __syncthreads();

        const int total = hist[0];
        int hi = hi_start;
        while (sh_nk < K_ && sh_Shi < total && hi > 0) {
            const int S_hi = sh_Shi;
            // lo = min i < hi with S[i] - S_hi <= BCAP
            int best = INT_MAX;
            #pragma unroll
            for (int j = 0; j < 4; j++) {
                int i = 4 * tid + j;
                if (i < hi && hist[i] - S_hi <= BCAP) best = min(best, i);
            }
            #pragma unroll
            for (int off = 16; off; off >>= 1)
                best = min(best, __shfl_down_sync(0xffffffffu, best, off));
            if (lane == 0) red[wrp] = best;
            __syncthreads();
            if (tid == 0) {
                int m = INT_MAX;
                #pragma unroll
                for (int w2 = 0; w2 < 8; w2++) m = min(m, red[w2]);
                sh_lo = (m >= hi) ? hi - 1 : m;
                sh_cnt = 0;
            }
            __syncthreads();
            const int lo = sh_lo;

            // extract band [lo, hi) by recomputing scores (rare, L2-hot)
            for (int n = tid; n < N_; n += 256) {
                float sc = score_at(b, c, n, conf0, cls0, conf1, cls1, conf2, cls2);
                if (sc > SCORE_T) {
                    int bkt = min((int)((sc - SCORE_T) * BSCALE), NBUCK - 1);
                    if (bkt >= lo && bkt < hi) {
                        int pos = atomicAdd(&sh_cnt, 1);
                        if (pos < BCAP)
                            keys[pos] = ((unsigned long long)__float_as_uint(sc) << 32)
                                      | (unsigned long long)(0x7FFF - n);
                    }
                }
            }
            __syncthreads();
            int bandc = min(sh_cnt, BCAP);

            if (bandc > 0) {
                bitonic_desc(keys, bandc, tid);
                for (int j = tid; j < bandc; j += 256) {
                    int n = 0x7FFF - (int)(keys[j] & 0x7FFFull);
                    const float* bb; int loc;
                    if (n < N0_)             { bb = bbox0; loc = b * N0_ + n; }
                    else if (n < N0_ + N1_)  { bb = bbox1; loc = b * N1_ + (n - N0_); }
                    else                     { bb = bbox2; loc = b * N2_ + (n - N0_ - N1_); }
                    float4 t = ((const float4*)bb)[loc];
                    t.x = fmaxf(t.x, 0.f); t.y = fmaxf(t.y, 0.f);
                    t.z = fmaxf(t.z, 0.f); t.w = fmaxf(t.w, 0.f);
                    c_box[j] = t;
                }
                __syncthreads();
                if (tid < 32)
                    greedy_walk(keys, c_box, bandc, lane, out_base, ky1, kx1, ky2, kx2, karea, &sh_nk);
            }
            if (tid == 0) sh_Shi = hist[lo];
            hi = lo;
            __syncthreads();
        }
    }

    __syncthreads();
    const int nkf = sh_nk;
    for (int kk = nkf + tid; kk < K_; kk += 256) {
        g_ks[out_base + kk] = NEG;
        ((float4*)g_kb)[out_base + kk] = make_float4(0.f, 0.f, 0.f, 0.f);
    }
}

// ---------------------------------------------------------------------------
// Kernel C: per-batch cross-class top-K via radix-select + warp-register pick.
// Output (f32): boxes [B,K,4] | scores [B,K] | cls [B,K] | valid [B]
// ---------------------------------------------------------------------------
__global__ __launch_bounds__(256) void topk_kernel(float* __restrict__ out)
{
    __shared__ unsigned s_sb[C_ * K_];            // 8 KB
    __shared__ int h2[4096];                      // 16 KB
    __shared__ int ct[256];
    __shared__ int wt[8];
    __shared__ int red[8];
    __shared__ unsigned long long list[128];
    __shared__ unsigned long long picks[K_];
    __shared__ int sh_m, sh_T;

    const int b    = blockIdx.x;
    const int tid  = threadIdx.x;
    const int lane = tid & 31;
    const int wrp  = tid >> 5;
    const int NE   = C_ * K_;                     // 2000

    for (int i = tid; i < 4096; i += 256) h2[i] = 0;
    if (tid == 0) sh_m = 0;
    __syncthreads();

    for (int i = tid; i < NE; i += 256) {
        float s = g_ks[b * NE + i];
        unsigned sb = (s > SCORE_T) ? __float_as_uint(s) : 0u;
        s_sb[i] = sb;
        if (sb) {
            int bk = min(max((int)(sb >> 11) - TK_BK0, 0), 4095);
            atomicAdd(&h2[bk], 1);
        }
    }
    __syncthreads();

    // suffix sum over 4096 buckets (16 per thread)
    {
        int s[16];
        int run = 0;
        #pragma unroll
        for (int j = 15; j >= 0; j--) { run += h2[16 * tid + j]; s[j] = run; }
        ct[tid] = run;
        __syncthreads();
        int v = ct[tid];
        #pragma unroll
        for (int off = 1; off < 32; off <<= 1) {
            int u = __shfl_down_sync(0xffffffffu, v, off);
            if (lane + off < 32) v += u;
        }
        if (lane == 0) wt[wrp] = v;
        __syncthreads();
        int addw = 0;
        #pragma unroll
        for (int w2 = 0; w2 < 8; w2++) if (w2 > wrp) addw += wt[w2];
        int T = v + addw - ct[tid];
        #pragma unroll
        for (int j = 0; j < 16; j++) h2[16 * tid + j] = T + s[j];
    }
    __syncthreads();

    // threshold bucket: T = max t with S[t] >= K_   (0 if none)
    {
        int bestt = -1;
        #pragma unroll
        for (int j = 0; j < 16; j++) {
            int i = 16 * tid + j;
            if (h2[i] >= K_) bestt = max(bestt, i);
        }
        #pragma unroll
        for (int off = 16; off; off >>= 1)
            bestt = max(bestt, __shfl_down_sync(0xffffffffu, bestt, off));
        if (lane == 0) red[wrp] = bestt;
        __syncthreads();
        if (tid == 0) {
            int m = -1;
            #pragma unroll
            for (int w2 = 0; w2 < 8; w2++) m = max(m, red[w2]);
            sh_T = max(m, 0);
        }
        __syncthreads();
    }
    const int T = sh_T;

    // compact survivors (bucket >= T)
    for (int i = tid; i < NE; i += 256) {
        unsigned sb = s_sb[i];
        if (sb) {
            int bk = min(max((int)(sb >> 11) - TK_BK0, 0), 4095);
            if (bk >= T) {
                int pos = atomicAdd(&sh_m, 1);
                if (pos < 128)
                    list[pos] = ((unsigned long long)sb << 32)
                              | (unsigned long long)(2047 - i);
            }
        }
    }
    __syncthreads();
    const int M = sh_m;

    if (M <= 128) {
        // warp-register top-25 (no block barriers)
        if (tid < 32) {
            unsigned long long q0 = (tid      < M) ? list[tid]      : 0ull;
            unsigned long long q1 = (tid + 32 < M) ? list[tid + 32] : 0ull;
            unsigned long long q2 = (tid + 64 < M) ? list[tid + 64] : 0ull;
            unsigned long long q3 = (tid + 96 < M) ? list[tid + 96] : 0ull;
            for (int k = 0; k < K_; k++) {
                unsigned long long lb = q0; int ls = 0;
                if (q1 > lb) { lb = q1; ls = 1; }
                if (q2 > lb) { lb = q2; ls = 2; }
                if (q3 > lb) { lb = q3; ls = 3; }
                unsigned long long wb = lb;
                int wi = (tid << 2) | ls;
                #pragma unroll
                for (int off = 16; off; off >>= 1) {
                    unsigned long long ob = __shfl_down_sync(0xffffffffu, wb, off);
                    int oi = __shfl_down_sync(0xffffffffu, wi, off);
                    if (ob > wb) { wb = ob; wi = oi; }
                }
                wb = __shfl_sync(0xffffffffu, wb, 0);
                wi = __shfl_sync(0xffffffffu, wi, 0);
                if (tid == 0) picks[k] = wb;
                if ((wi >> 2) == tid && wb) {
                    int s2 = wi & 3;
                    if (s2 == 0) q0 = 0; else if (s2 == 1) q1 = 0;
                    else if (s2 == 2) q2 = 0; else q3 = 0;
                }
            }
        }
    } else {
        // guard path: iterative block argmax over all entries
        for (int k = 0; k < K_; k++) {
            unsigned long long bk = 0ull;
            for (int i = tid; i < NE; i += 256) {
                unsigned sb = s_sb[i];
                if (sb) {
                    unsigned long long kk = ((unsigned long long)sb << 32)
                                          | (unsigned long long)(2047 - i);
                    if (kk > bk) bk = kk;
                }
            }
            #pragma unroll
            for (int off = 16; off; off >>= 1) {
                unsigned long long o = __shfl_down_sync(0xffffffffu, bk, off);
                if (o > bk) bk = o;
            }
            if (lane == 0) list[wrp] = bk;
            __syncthreads();
            if (tid == 0) {
                unsigned long long m = 0ull;
                #pragma unroll
                for (int w2 = 0; w2 < 8; w2++) if (list[w2] > m) m = list[w2];
                picks[k] = m;
                if (m) s_sb[2047 - (int)(m & 0x7FFull)] = 0u;
            }
            __syncthreads();
        }
    }
    __syncthreads();

    const int OB_scores = B_ * K_ * 4;
    const int OB_cls    = OB_scores + B_ * K_;
    const int OB_valid  = OB_cls + B_ * K_;

    if (tid < K_) {
        unsigned long long key = picks[tid];
        float s = __uint_as_float((unsigned)(key >> 32));
        bool valid = s > SCORE_T;
        int flat = 2047 - (int)(key & 0x7FFull);
        float4 bx = make_float4(0.f, 0.f, 0.f, 0.f);
        float cid = 0.f;
        if (valid) {
            bx = ((float4*)g_kb)[b * NE + flat];
            bx.x = fminf(fmaxf(bx.x, 0.f), 1.f);
            bx.y = fminf(fmaxf(bx.y, 0.f), 1.f);
            bx.z = fminf(fmaxf(bx.z, 0.f), 1.f);
            bx.w = fminf(fmaxf(bx.w, 0.f), 1.f);
            cid = (float)(flat / K_);
        }
        int o = b * K_ + tid;
        ((float4*)out)[o]  = bx;
        out[OB_scores + o] = valid ? s : 0.f;
        out[OB_cls + o]    = cid;
    }
    if (tid < 32) {
        bool v = (tid < K_) &&
                 (__uint_as_float((unsigned)(picks[tid] >> 32)) > SCORE_T);
        unsigned m = __ballot_sync(0xffffffffu, v);
        if (tid == 0) out[OB_valid + b] = (float)__popc(m);
    }
}

// ---------------------------------------------------------------------------
extern "C" void kernel_launch(void* const* d_in, const int* in_sizes, int n_in,
                              void* d_out, int out_size)
{
    const float* bbox0 = (const float*)d_in[0];
    const float* conf0 = (const float*)d_in[1];
    const float* cls0  = (const float*)d_in[2];
    const float* bbox1 = (const float*)d_in[3];
    const float* conf1 = (const float*)d_in[4];
    const float* cls1  = (const float*)d_in[5];
    const float* bbox2 = (const float*)d_in[6];
    const float* conf2 = (const float*)d_in[7];
    const float* cls2  = (const float*)d_in[8];

    zero_kernel<<<(NCELL + 255) / 256, 256>>>();
    band_scatter<<<1184, 256>>>(conf0, cls0, conf1, cls1, conf2, cls2);
    nms_kernel<<<NCELL, 256>>>(bbox0, bbox1, bbox2,
                               conf0, cls0, conf1, cls1, conf2, cls2);
    topk_kernel<<<B_, 256>>>((float*)d_out);
}